// round 14
// baseline (speedup 1.0000x reference)
#include <cuda_runtime.h>
#include <math.h>

#define HWp 16384
#define Hp  128
#define Wp  128
#define Bp  4
#define Cp  64
#define CKp 576

// ---------------- scratch (device globals: allocation-free) ----------------
__device__ float g_x1  [Bp*Cp *HWp];   // encoder output
__device__ float g_t128[Bp*128*HWp];   // convnext hidden
__device__ float g_e1  [Bp*Cp *HWp];   // 64-ch ping
__device__ float g_e2  [Bp*Cp *HWp];   // 64-ch pong
__device__ float g_off [Bp*18 *HWp];   // offsets
__device__ float g_xb  [Bp*CKp*HWp];   // deform output
__device__ float g_dct [Bp*CKp*HWp];
__device__ float g_wa  [Bp*CKp*HWp];
__device__ float g_wb  [Bp*CKp*HWp];

// ============================================================================
// Generic 1x1-conv / implicit-3x3-conv GEMM.
//   out[b, m, p] = act( sum_k W[m,k] * X[k, p] + bias[m] ) (+ addsrc)
// 1x1:  X[k,p] = in[b,k,p], Ktot = Cin
// 3x3:  X[ci*9+tap, p] = in[b,ci, shifted p] (zero pad), Ktot = Cin*9
// Tile: 64 outputs x 64 pixels, BK=16, 256 threads, 4x4 microtile.
// Pixel tiles (64 wide) never cross a row since Wp=128.
// ACT: 0=none 1=relu 2=leaky0.1 3=8*tanh
// ============================================================================
template<int ACT, bool K3>
__global__ __launch_bounds__(256)
void gemm_kernel(const float* __restrict__ in, const float* __restrict__ Wt,
                 const float* __restrict__ bias, const float* __restrict__ addsrc,
                 float* __restrict__ out, int Cin, int Cout, int Ktot)
{
    __shared__ float Ws[16][64];
    __shared__ float Xs[16][64];

    const int t  = threadIdx.x;
    const int tx = t & 15;
    const int ty = t >> 4;
    const int p0 = blockIdx.x * 64;
    const int m0 = blockIdx.y * 64;
    const int bz = blockIdx.z;
    const int h  = p0 >> 7;
    const int w0 = p0 & 127;

    const int wm  = t >> 2;          // 0..63  (output row for W load)
    const int wkq = (t & 3) * 4;     // 0,4,8,12
    const int xk  = t >> 4;          // 0..15  (k row for X load)
    const int xn  = (t & 15) * 4;    // pixel quad

    float acc[4][4] = {};

    for (int kt = 0; kt < Ktot; kt += 16) {
        // ---- W tile: Ws[k][m] = W[m0+m, kt+k]
        float4 wv = make_float4(0.f, 0.f, 0.f, 0.f);
        if (m0 + wm < Cout)
            wv = *(const float4*)(Wt + (size_t)(m0 + wm) * Ktot + kt + wkq);
        Ws[wkq + 0][wm] = wv.x;
        Ws[wkq + 1][wm] = wv.y;
        Ws[wkq + 2][wm] = wv.z;
        Ws[wkq + 3][wm] = wv.w;

        // ---- X tile
        if (!K3) {
            const float* src = in + (size_t)(bz * Cin + kt + xk) * HWp + p0 + xn;
            *(float4*)&Xs[xk][xn] = *(const float4*)src;
        } else {
            const int kk  = kt + xk;
            const int ci  = kk / 9;
            const int tap = kk - ci * 9;
            const int dy  = tap / 3 - 1;
            const int dx  = tap - (tap / 3) * 3 - 1;
            const int hh  = h + dy;
            float v0 = 0.f, v1 = 0.f, v2 = 0.f, v3 = 0.f;
            if (hh >= 0 && hh < Hp) {
                const float* row = in + (size_t)(bz * Cin + ci) * HWp + (hh << 7);
                const int wbase = w0 + xn + dx;
                int ww;
                ww = wbase + 0; if (ww >= 0 && ww < Wp) v0 = row[ww];
                ww = wbase + 1; if (ww >= 0 && ww < Wp) v1 = row[ww];
                ww = wbase + 2; if (ww >= 0 && ww < Wp) v2 = row[ww];
                ww = wbase + 3; if (ww >= 0 && ww < Wp) v3 = row[ww];
            }
            Xs[xk][xn + 0] = v0;
            Xs[xk][xn + 1] = v1;
            Xs[xk][xn + 2] = v2;
            Xs[xk][xn + 3] = v3;
        }
        __syncthreads();

        #pragma unroll
        for (int kk = 0; kk < 16; kk++) {
            const float4 a = *(const float4*)&Ws[kk][ty * 4];
            const float4 x = *(const float4*)&Xs[kk][tx * 4];
            acc[0][0] += a.x * x.x; acc[0][1] += a.x * x.y; acc[0][2] += a.x * x.z; acc[0][3] += a.x * x.w;
            acc[1][0] += a.y * x.x; acc[1][1] += a.y * x.y; acc[1][2] += a.y * x.z; acc[1][3] += a.y * x.w;
            acc[2][0] += a.z * x.x; acc[2][1] += a.z * x.y; acc[2][2] += a.z * x.z; acc[2][3] += a.z * x.w;
            acc[3][0] += a.w * x.x; acc[3][1] += a.w * x.y; acc[3][2] += a.w * x.z; acc[3][3] += a.w * x.w;
        }
        __syncthreads();
    }

    #pragma unroll
    for (int i = 0; i < 4; i++) {
        const int m = m0 + ty * 4 + i;
        if (m >= Cout) continue;
        const float bv = bias ? bias[m] : 0.f;
        #pragma unroll
        for (int j = 0; j < 4; j++) {
            const int p = p0 + tx * 4 + j;
            float v = acc[i][j] + bv;
            if (ACT == 1)      v = fmaxf(v, 0.f);
            else if (ACT == 2) v = (v >= 0.f) ? v : 0.1f * v;
            else if (ACT == 3) v = 8.f * tanhf(v);
            const size_t oi = (size_t)(bz * Cout + m) * HWp + p;
            if (addsrc) v += addsrc[oi];
            out[oi] = v;
        }
    }
}

// ============================================================================
// Depthwise 7x7, pad 3, 64 channels
// ============================================================================
__global__ __launch_bounds__(256)
void dw7_kernel(const float* __restrict__ in, const float* __restrict__ w,
                float* __restrict__ out)
{
    const int p = blockIdx.x * 256 + threadIdx.x;
    const int c = blockIdx.y, b = blockIdx.z;
    const int h = p >> 7, x = p & 127;
    const float* base = in + (size_t)(b * Cp + c) * HWp;
    const float* wc = w + c * 49;
    float acc = 0.f;
    #pragma unroll
    for (int i = 0; i < 7; i++) {
        const int hh = h + i - 3;
        if (hh < 0 || hh >= Hp) continue;
        const float* row = base + (hh << 7);
        #pragma unroll
        for (int j = 0; j < 7; j++) {
            const int ww = x + j - 3;
            if (ww >= 0 && ww < Wp) acc += row[ww] * wc[i * 7 + j];
        }
    }
    out[(size_t)(b * Cp + c) * HWp + p] = acc;
}

// ============================================================================
// Depthwise 3x3, pad 1, 576 channels. ACT: 1=relu, 4=sigmoid
// ============================================================================
template<int ACT>
__global__ __launch_bounds__(256)
void dw3_kernel(const float* __restrict__ in, const float* __restrict__ w,
                float* __restrict__ out)
{
    const int p = blockIdx.x * 256 + threadIdx.x;
    const int c = blockIdx.y, b = blockIdx.z;
    const int h = p >> 7, x = p & 127;
    const float* base = in + (size_t)(b * CKp + c) * HWp;
    const float* wc = w + c * 9;
    float acc = 0.f;
    #pragma unroll
    for (int i = 0; i < 3; i++) {
        const int hh = h + i - 1;
        if (hh < 0 || hh >= Hp) continue;
        const float* row = base + (hh << 7);
        #pragma unroll
        for (int j = 0; j < 3; j++) {
            const int ww = x + j - 1;
            if (ww >= 0 && ww < Wp) acc += row[ww] * wc[i * 3 + j];
        }
    }
    if (ACT == 1)      acc = fmaxf(acc, 0.f);
    else if (ACT == 4) acc = 1.f / (1.f + expf(-acc));
    out[(size_t)(b * CKp + c) * HWp + p] = acc;
}

// ============================================================================
// Deformable neighbourhood gather: xb[b, c*9+k, p] = bilinear(x1[b,c], p+off_k)
// Zero outside (valid mask per corner), indices clamped for the gather.
// One thread per (b, k, p); 4 corners computed once, reused over 64 channels.
// ============================================================================
__global__ __launch_bounds__(128)
void deform_kernel(const float* __restrict__ x1, const float* __restrict__ off,
                   float* __restrict__ xb)
{
    const int p = blockIdx.x * 128 + threadIdx.x;
    const int k = blockIdx.y, b = blockIdx.z;
    const int h = p >> 7, wpx = p & 127;

    const float dy = off[(size_t)(b * 18 + 2 * k + 0) * HWp + p];
    const float dx = off[(size_t)(b * 18 + 2 * k + 1) * HWp + p];

    const float py = (float)h   + (float)(k / 3 - 1) + dy;
    const float px = (float)wpx + (float)(k % 3 - 1) + dx;

    const float y0f = floorf(py), x0f = floorf(px);
    const float wy1 = py - y0f, wx1 = px - x0f;
    const float wy0 = 1.f - wy1, wx0 = 1.f - wx1;

    const int y0 = (int)y0f, x0 = (int)x0f;
    const int y1 = y0 + 1, x1i = x0 + 1;

    const bool vy0 = (y0 >= 0 && y0 < Hp), vy1 = (y1 >= 0 && y1 < Hp);
    const bool vx0 = (x0 >= 0 && x0 < Wp), vx1 = (x1i >= 0 && x1i < Wp);

    const int yc0 = min(max(y0, 0), Hp - 1), yc1 = min(max(y1, 0), Hp - 1);
    const int xc0 = min(max(x0, 0), Wp - 1), xc1 = min(max(x1i, 0), Wp - 1);

    const float w00 = (vy0 && vx0) ? wy0 * wx0 : 0.f;
    const float w01 = (vy0 && vx1) ? wy0 * wx1 : 0.f;
    const float w10 = (vy1 && vx0) ? wy1 * wx0 : 0.f;
    const float w11 = (vy1 && vx1) ? wy1 * wx1 : 0.f;

    const int i00 = yc0 * Wp + xc0, i01 = yc0 * Wp + xc1;
    const int i10 = yc1 * Wp + xc0, i11 = yc1 * Wp + xc1;

    for (int c = 0; c < Cp; c++) {
        const float* xc = x1 + (size_t)(b * Cp + c) * HWp;
        const float v = w00 * xc[i00] + w01 * xc[i01] + w10 * xc[i10] + w11 * xc[i11];
        xb[(size_t)(b * CKp + c * 9 + k) * HWp + p] = v;
    }
}

// ============================================================================
// Grouped per-c 9x9 matmul: out[b, c*9+j, p] = sum_k w[(c*9+j)*9+k] * v_k
// where v_k = a[b, c*9+k, p]  (optionally * bmul for wiener*dct fusion).
// ============================================================================
template<bool MUL>
__global__ __launch_bounds__(256)
void grp9_kernel(const float* __restrict__ a, const float* __restrict__ bmul,
                 const float* __restrict__ w, float* __restrict__ out)
{
    const int p = blockIdx.x * 256 + threadIdx.x;
    const int c = blockIdx.y, b = blockIdx.z;
    __shared__ float ws[81];
    if (threadIdx.x < 81) ws[threadIdx.x] = w[c * 81 + threadIdx.x];
    __syncthreads();

    float v[9];
    #pragma unroll
    for (int k = 0; k < 9; k++) {
        const size_t idx = (size_t)(b * CKp + c * 9 + k) * HWp + p;
        v[k] = MUL ? (a[idx] * bmul[idx]) : a[idx];
    }
    #pragma unroll
    for (int j = 0; j < 9; j++) {
        float o = 0.f;
        #pragma unroll
        for (int k = 0; k < 9; k++) o += ws[j * 9 + k] * v[k];
        out[(size_t)(b * CKp + c * 9 + j) * HWp + p] = o;
    }
}

// ============================================================================
// Host side
// ============================================================================
static void launch_gemm(const float* in, const float* W, const float* bias,
                        const float* add, float* out,
                        int Cin, int Cout, int Ktot, int act, bool k3)
{
    dim3 grid(HWp / 64, (Cout + 63) / 64, Bp);
    if (!k3) {
        switch (act) {
        case 0: gemm_kernel<0, false><<<grid, 256>>>(in, W, bias, add, out, Cin, Cout, Ktot); break;
        case 1: gemm_kernel<1, false><<<grid, 256>>>(in, W, bias, add, out, Cin, Cout, Ktot); break;
        case 2: gemm_kernel<2, false><<<grid, 256>>>(in, W, bias, add, out, Cin, Cout, Ktot); break;
        case 3: gemm_kernel<3, false><<<grid, 256>>>(in, W, bias, add, out, Cin, Cout, Ktot); break;
        }
    } else {
        switch (act) {
        case 0: gemm_kernel<0, true><<<grid, 256>>>(in, W, bias, add, out, Cin, Cout, Ktot); break;
        case 2: gemm_kernel<2, true><<<grid, 256>>>(in, W, bias, add, out, Cin, Cout, Ktot); break;
        }
    }
}

extern "C" void kernel_launch(void* const* d_in, const int* in_sizes, int n_in,
                              void* d_out, int out_size)
{
    (void)in_sizes; (void)n_in; (void)out_size;
    const float* x       = (const float*)d_in[0];
    const float* enc_dw  = (const float*)d_in[1];
    const float* enc_pw1 = (const float*)d_in[2];
    const float* enc_pw2 = (const float*)d_in[3];
    const float* dec_dw  = (const float*)d_in[4];
    const float* dec_pw1 = (const float*)d_in[5];
    const float* dec_pw2 = (const float*)d_in[6];
    const float* off_w1  = (const float*)d_in[7];
    const float* off_b1  = (const float*)d_in[8];
    const float* off_w2  = (const float*)d_in[9];
    const float* off_b2  = (const float*)d_in[10];
    const float* off_w3  = (const float*)d_in[11];
    const float* off_b3  = (const float*)d_in[12];
    const float* off_w4  = (const float*)d_in[13];
    const float* off_b4  = (const float*)d_in[14];
    const float* off_w5  = (const float*)d_in[15];
    const float* off_b5  = (const float*)d_in[16];
    const float* off_w6  = (const float*)d_in[17];
    const float* off_b6  = (const float*)d_in[18];
    const float* dct_w   = (const float*)d_in[19];
    const float* wie_w1  = (const float*)d_in[20];
    const float* wie_w2  = (const float*)d_in[21];
    const float* wie_w3  = (const float*)d_in[22];
    const float* wie_w4  = (const float*)d_in[23];
    const float* wie_w5  = (const float*)d_in[24];
    const float* wie_w6  = (const float*)d_in[25];
    const float* inv_w1  = (const float*)d_in[26];
    const float* inv_w2  = (const float*)d_in[27];

    float *x1, *t128, *e1, *e2, *off, *xb, *dct, *wa, *wb;
    cudaGetSymbolAddress((void**)&x1,   g_x1);
    cudaGetSymbolAddress((void**)&t128, g_t128);
    cudaGetSymbolAddress((void**)&e1,   g_e1);
    cudaGetSymbolAddress((void**)&e2,   g_e2);
    cudaGetSymbolAddress((void**)&off,  g_off);
    cudaGetSymbolAddress((void**)&xb,   g_xb);
    cudaGetSymbolAddress((void**)&dct,  g_dct);
    cudaGetSymbolAddress((void**)&wa,   g_wa);
    cudaGetSymbolAddress((void**)&wb,   g_wb);

    const dim3 gdw(HWp / 256, Cp, Bp);
    const dim3 gdw3(HWp / 256, CKp, Bp);
    const dim3 ggrp(HWp / 256, Cp, Bp);

    // ---- Encoder ConvNeXt: x1 = x + pw2(relu(pw1(dw7(x)))) ----
    dw7_kernel<<<gdw, 256>>>(x, enc_dw, e1);
    launch_gemm(e1, enc_pw1, nullptr, nullptr, t128, 64, 128, 64, 1, false);
    launch_gemm(t128, enc_pw2, nullptr, x, x1, 128, 64, 128, 0, false);

    // ---- Offset CNN: 8*tanh applied on final conv ----
    launch_gemm(x1, off_w1, off_b1, nullptr, e1, 64, 64, 64, 2, false);
    launch_gemm(e1, off_w2, off_b2, nullptr, e2, 64, 64, 576, 2, true);
    launch_gemm(e2, off_w3, off_b3, nullptr, e1, 64, 64, 576, 2, true);
    launch_gemm(e1, off_w4, off_b4, nullptr, e2, 64, 64, 576, 2, true);
    launch_gemm(e2, off_w5, off_b5, nullptr, e1, 64, 64, 576, 2, true);
    launch_gemm(e1, off_w6, off_b6, nullptr, off, 64, 18, 64, 3, false);

    // ---- Deformable gather ----
    deform_kernel<<<dim3(HWp / 128, 9, Bp), 128>>>(x1, off, xb);

    // ---- DCT (grouped per-c 9x9) ----
    grp9_kernel<false><<<ggrp, 256>>>(xb, nullptr, dct_w, dct);

    // ---- Wiener chain ----
    launch_gemm(xb, wie_w1, nullptr, nullptr, wa, 576, 576, 576, 0, false);
    dw3_kernel<1><<<gdw3, 256>>>(wa, wie_w2, wb);
    launch_gemm(wb, wie_w3, nullptr, nullptr, wa, 576, 576, 576, 0, false);
    dw3_kernel<1><<<gdw3, 256>>>(wa, wie_w4, wb);
    launch_gemm(wb, wie_w5, nullptr, nullptr, wa, 576, 576, 576, 0, false);
    dw3_kernel<4><<<gdw3, 256>>>(wa, wie_w6, wb);   // sigmoid -> wiener in wb

    // ---- Inverse: (wiener*dct) -> grouped 9x9 (inv_w1) -> 1x1 (inv_w2) ----
    grp9_kernel<true><<<ggrp, 256>>>(wb, dct, inv_w1, wa);
    launch_gemm(wa, inv_w2, nullptr, nullptr, e1, 576, 64, 576, 0, false);

    // ---- Decoder ConvNeXt: out = e1 + pw2(relu(pw1(dw7(e1)))) ----
    dw7_kernel<<<gdw, 256>>>(e1, dec_dw, e2);
    launch_gemm(e2, dec_pw1, nullptr, nullptr, t128, 64, 128, 64, 1, false);
    launch_gemm(t128, dec_pw2, nullptr, e1, (float*)d_out, 128, 64, 128, 0, false);
}

// round 15
// speedup vs baseline: 2.0916x; 2.0916x over previous
#include <cuda_runtime.h>
#include <math.h>
#include <stdint.h>

#define HWp 16384
#define Hp  128
#define Wp  128
#define Bp  4
#define Cp  64
#define CKp 576

// ---------------- scratch (device globals: allocation-free) ----------------
__device__ float g_x1  [Bp*Cp *HWp];   // encoder output
__device__ float g_t128[Bp*128*HWp];   // convnext hidden
__device__ float g_e1  [Bp*Cp *HWp];   // 64-ch ping
__device__ float g_e2  [Bp*Cp *HWp];   // 64-ch pong
__device__ float g_off [Bp*18 *HWp];   // offsets
__device__ float g_xb  [Bp*CKp*HWp];   // deform output
__device__ float g_dct [Bp*CKp*HWp];
__device__ float g_wa  [Bp*CKp*HWp];
__device__ float g_wb  [Bp*CKp*HWp];

// ============================================================================
// tf32 helpers
// ============================================================================
__device__ __forceinline__ uint32_t f2tf(float x) {
    uint32_t r;
    asm("cvt.rna.tf32.f32 %0, %1;" : "=r"(r) : "f"(x));
    return r;
}

__device__ __forceinline__ void mma_tf32(float* d, const uint32_t* a, const uint32_t* b) {
    asm volatile(
        "mma.sync.aligned.m16n8k8.row.col.f32.tf32.tf32.f32 "
        "{%0,%1,%2,%3},{%4,%5,%6,%7},{%8,%9},{%0,%1,%2,%3};\n"
        : "+f"(d[0]), "+f"(d[1]), "+f"(d[2]), "+f"(d[3])
        : "r"(a[0]), "r"(a[1]), "r"(a[2]), "r"(a[3]), "r"(b[0]), "r"(b[1]));
}

// ============================================================================
// tf32 tensor-core 1x1-conv GEMM.
//   out[b,m,p] = act( sum_k W[m,k] * in[b,k,p] ) (+ addsrc)
// Requires: Cout % 64 == 0, Ktot % 32 == 0 (true for all users: 64/128/576).
// Tile: BM=64 channels x BN=128 pixels (one full image row), BK=32.
// 128 threads = 4 warps in 2x2; warp tile 32x64 = 2 m-frags x 8 n-frags of
// m16n8k8. Smem row strides 36 (A) / 136 (B) -> conflict-free frag loads.
// ACT: 0=none 1=relu
// ============================================================================
template<int ACT, bool ADD>
__global__ __launch_bounds__(128)
void tgemm_kernel(const float* __restrict__ in, const float* __restrict__ Wt,
                  const float* __restrict__ addsrc, float* __restrict__ out,
                  int Cin, int Cout, int Ktot)
{
    __shared__ uint32_t As[64 * 36];   // [m][k], stride 36
    __shared__ uint32_t Bs[32 * 136];  // [k][n], stride 136

    const int t    = threadIdx.x;
    const int warp = t >> 5;
    const int lane = t & 31;
    const int g    = lane >> 2;   // groupID (0..7)
    const int tg   = lane & 3;    // thread-in-group (0..3)

    const int p0 = blockIdx.x * 128;
    const int m0 = blockIdx.y * 64;
    const int bz = blockIdx.z;

    const int wm0 = (warp & 1) * 32;   // warp M offset within BM
    const int wn0 = (warp >> 1) * 64;  // warp N offset within BN

    float acc[2][8][4];
    #pragma unroll
    for (int i = 0; i < 2; i++)
        #pragma unroll
        for (int j = 0; j < 8; j++)
            acc[i][j][0] = acc[i][j][1] = acc[i][j][2] = acc[i][j][3] = 0.f;

    for (int kt = 0; kt < Ktot; kt += 32) {
        // ---- A tile: W[m0+m][kt+k] -> As[m*36+k], 64x32, 4 float4 per thread
        #pragma unroll
        for (int q = 0; q < 4; q++) {
            const int fid = q * 128 + t;
            const int m   = fid >> 3;
            const int kq  = (fid & 7) * 4;
            const float4 v = *(const float4*)(Wt + (size_t)(m0 + m) * Ktot + kt + kq);
            uint32_t* dst = &As[m * 36 + kq];
            dst[0] = f2tf(v.x); dst[1] = f2tf(v.y); dst[2] = f2tf(v.z); dst[3] = f2tf(v.w);
        }
        // ---- B tile: in[b][kt+k][p0+n] -> Bs[k*136+n], 32x128, 8 float4/thr
        #pragma unroll
        for (int q = 0; q < 8; q++) {
            const int fid = q * 128 + t;
            const int k   = fid >> 5;
            const int nq  = (fid & 31) * 4;
            const float4 v = *(const float4*)(in + (size_t)(bz * Cin + kt + k) * HWp + p0 + nq);
            uint32_t* dst = &Bs[k * 136 + nq];
            dst[0] = f2tf(v.x); dst[1] = f2tf(v.y); dst[2] = f2tf(v.z); dst[3] = f2tf(v.w);
        }
        __syncthreads();

        #pragma unroll
        for (int ks = 0; ks < 32; ks += 8) {
            uint32_t a[2][4], b[8][2];
            #pragma unroll
            for (int i = 0; i < 2; i++) {
                const int r0 = wm0 + i * 16 + g;
                a[i][0] = As[r0 * 36 + ks + tg];
                a[i][1] = As[(r0 + 8) * 36 + ks + tg];
                a[i][2] = As[r0 * 36 + ks + tg + 4];
                a[i][3] = As[(r0 + 8) * 36 + ks + tg + 4];
            }
            #pragma unroll
            for (int j = 0; j < 8; j++) {
                const int cn = wn0 + j * 8 + g;
                b[j][0] = Bs[(ks + tg) * 136 + cn];
                b[j][1] = Bs[(ks + tg + 4) * 136 + cn];
            }
            #pragma unroll
            for (int i = 0; i < 2; i++)
                #pragma unroll
                for (int j = 0; j < 8; j++)
                    mma_tf32(acc[i][j], a[i], b[j]);
        }
        __syncthreads();
    }

    // ---- Epilogue: c0=[g][2tg], c1=[g][2tg+1], c2=[g+8][2tg], c3=[g+8][2tg+1]
    #pragma unroll
    for (int i = 0; i < 2; i++) {
        const int mA = m0 + wm0 + i * 16 + g;
        const int mB = mA + 8;
        #pragma unroll
        for (int j = 0; j < 8; j++) {
            const int p = p0 + wn0 + j * 8 + 2 * tg;
            float2 vA = make_float2(acc[i][j][0], acc[i][j][1]);
            float2 vB = make_float2(acc[i][j][2], acc[i][j][3]);
            if (ACT == 1) {
                vA.x = fmaxf(vA.x, 0.f); vA.y = fmaxf(vA.y, 0.f);
                vB.x = fmaxf(vB.x, 0.f); vB.y = fmaxf(vB.y, 0.f);
            }
            const size_t oA = (size_t)(bz * Cout + mA) * HWp + p;
            const size_t oB = (size_t)(bz * Cout + mB) * HWp + p;
            if (ADD) {
                const float2 rA = *(const float2*)(addsrc + oA);
                const float2 rB = *(const float2*)(addsrc + oB);
                vA.x += rA.x; vA.y += rA.y;
                vB.x += rB.x; vB.y += rB.y;
            }
            *(float2*)(out + oA) = vA;
            *(float2*)(out + oB) = vB;
        }
    }
}

// ============================================================================
// fp32 scalar GEMM (kept for the precision-sensitive encoder + offset CNN).
// ACT: 0=none 1=relu 2=leaky0.1 3=8*tanh
// ============================================================================
template<int ACT, bool K3>
__global__ __launch_bounds__(256)
void gemm_kernel(const float* __restrict__ in, const float* __restrict__ Wt,
                 const float* __restrict__ bias, const float* __restrict__ addsrc,
                 float* __restrict__ out, int Cin, int Cout, int Ktot)
{
    __shared__ float Ws[16][64];
    __shared__ float Xs[16][64];

    const int t  = threadIdx.x;
    const int tx = t & 15;
    const int ty = t >> 4;
    const int p0 = blockIdx.x * 64;
    const int m0 = blockIdx.y * 64;
    const int bz = blockIdx.z;
    const int h  = p0 >> 7;
    const int w0 = p0 & 127;

    const int wm  = t >> 2;
    const int wkq = (t & 3) * 4;
    const int xk  = t >> 4;
    const int xn  = (t & 15) * 4;

    float acc[4][4] = {};

    for (int kt = 0; kt < Ktot; kt += 16) {
        float4 wv = make_float4(0.f, 0.f, 0.f, 0.f);
        if (m0 + wm < Cout)
            wv = *(const float4*)(Wt + (size_t)(m0 + wm) * Ktot + kt + wkq);
        Ws[wkq + 0][wm] = wv.x;
        Ws[wkq + 1][wm] = wv.y;
        Ws[wkq + 2][wm] = wv.z;
        Ws[wkq + 3][wm] = wv.w;

        if (!K3) {
            const float* src = in + (size_t)(bz * Cin + kt + xk) * HWp + p0 + xn;
            *(float4*)&Xs[xk][xn] = *(const float4*)src;
        } else {
            const int kk  = kt + xk;
            const int ci  = kk / 9;
            const int tap = kk - ci * 9;
            const int dy  = tap / 3 - 1;
            const int dx  = tap - (tap / 3) * 3 - 1;
            const int hh  = h + dy;
            float v0 = 0.f, v1 = 0.f, v2 = 0.f, v3 = 0.f;
            if (hh >= 0 && hh < Hp) {
                const float* row = in + (size_t)(bz * Cin + ci) * HWp + (hh << 7);
                const int wbase = w0 + xn + dx;
                int ww;
                ww = wbase + 0; if (ww >= 0 && ww < Wp) v0 = row[ww];
                ww = wbase + 1; if (ww >= 0 && ww < Wp) v1 = row[ww];
                ww = wbase + 2; if (ww >= 0 && ww < Wp) v2 = row[ww];
                ww = wbase + 3; if (ww >= 0 && ww < Wp) v3 = row[ww];
            }
            Xs[xk][xn + 0] = v0;
            Xs[xk][xn + 1] = v1;
            Xs[xk][xn + 2] = v2;
            Xs[xk][xn + 3] = v3;
        }
        __syncthreads();

        #pragma unroll
        for (int kk = 0; kk < 16; kk++) {
            const float4 a = *(const float4*)&Ws[kk][ty * 4];
            const float4 x = *(const float4*)&Xs[kk][tx * 4];
            acc[0][0] += a.x * x.x; acc[0][1] += a.x * x.y; acc[0][2] += a.x * x.z; acc[0][3] += a.x * x.w;
            acc[1][0] += a.y * x.x; acc[1][1] += a.y * x.y; acc[1][2] += a.y * x.z; acc[1][3] += a.y * x.w;
            acc[2][0] += a.z * x.x; acc[2][1] += a.z * x.y; acc[2][2] += a.z * x.z; acc[2][3] += a.z * x.w;
            acc[3][0] += a.w * x.x; acc[3][1] += a.w * x.y; acc[3][2] += a.w * x.z; acc[3][3] += a.w * x.w;
        }
        __syncthreads();
    }

    #pragma unroll
    for (int i = 0; i < 4; i++) {
        const int m = m0 + ty * 4 + i;
        if (m >= Cout) continue;
        const float bv = bias ? bias[m] : 0.f;
        #pragma unroll
        for (int j = 0; j < 4; j++) {
            const int p = p0 + tx * 4 + j;
            float v = acc[i][j] + bv;
            if (ACT == 1)      v = fmaxf(v, 0.f);
            else if (ACT == 2) v = (v >= 0.f) ? v : 0.1f * v;
            else if (ACT == 3) v = 8.f * tanhf(v);
            const size_t oi = (size_t)(bz * Cout + m) * HWp + p;
            if (addsrc) v += addsrc[oi];
            out[oi] = v;
        }
    }
}

// ============================================================================
// Depthwise 7x7, pad 3, 64 channels
// ============================================================================
__global__ __launch_bounds__(256)
void dw7_kernel(const float* __restrict__ in, const float* __restrict__ w,
                float* __restrict__ out)
{
    const int p = blockIdx.x * 256 + threadIdx.x;
    const int c = blockIdx.y, b = blockIdx.z;
    const int h = p >> 7, x = p & 127;
    const float* base = in + (size_t)(b * Cp + c) * HWp;
    const float* wc = w + c * 49;
    float acc = 0.f;
    #pragma unroll
    for (int i = 0; i < 7; i++) {
        const int hh = h + i - 3;
        if (hh < 0 || hh >= Hp) continue;
        const float* row = base + (hh << 7);
        #pragma unroll
        for (int j = 0; j < 7; j++) {
            const int ww = x + j - 3;
            if (ww >= 0 && ww < Wp) acc += row[ww] * wc[i * 7 + j];
        }
    }
    out[(size_t)(b * Cp + c) * HWp + p] = acc;
}

// ============================================================================
// Depthwise 3x3, pad 1, 576 channels. ACT: 1=relu, 4=sigmoid
// ============================================================================
template<int ACT>
__global__ __launch_bounds__(256)
void dw3_kernel(const float* __restrict__ in, const float* __restrict__ w,
                float* __restrict__ out)
{
    const int p = blockIdx.x * 256 + threadIdx.x;
    const int c = blockIdx.y, b = blockIdx.z;
    const int h = p >> 7, x = p & 127;
    const float* base = in + (size_t)(b * CKp + c) * HWp;
    const float* wc = w + c * 9;
    float acc = 0.f;
    #pragma unroll
    for (int i = 0; i < 3; i++) {
        const int hh = h + i - 1;
        if (hh < 0 || hh >= Hp) continue;
        const float* row = base + (hh << 7);
        #pragma unroll
        for (int j = 0; j < 3; j++) {
            const int ww = x + j - 1;
            if (ww >= 0 && ww < Wp) acc += row[ww] * wc[i * 3 + j];
        }
    }
    if (ACT == 1)      acc = fmaxf(acc, 0.f);
    else if (ACT == 4) acc = 1.f / (1.f + expf(-acc));
    out[(size_t)(b * CKp + c) * HWp + p] = acc;
}

// ============================================================================
// Deformable neighbourhood gather
// ============================================================================
__global__ __launch_bounds__(128)
void deform_kernel(const float* __restrict__ x1, const float* __restrict__ off,
                   float* __restrict__ xb)
{
    const int p = blockIdx.x * 128 + threadIdx.x;
    const int k = blockIdx.y, b = blockIdx.z;
    const int h = p >> 7, wpx = p & 127;

    const float dy = off[(size_t)(b * 18 + 2 * k + 0) * HWp + p];
    const float dx = off[(size_t)(b * 18 + 2 * k + 1) * HWp + p];

    const float py = (float)h   + (float)(k / 3 - 1) + dy;
    const float px = (float)wpx + (float)(k % 3 - 1) + dx;

    const float y0f = floorf(py), x0f = floorf(px);
    const float wy1 = py - y0f, wx1 = px - x0f;
    const float wy0 = 1.f - wy1, wx0 = 1.f - wx1;

    const int y0 = (int)y0f, x0 = (int)x0f;
    const int y1 = y0 + 1, x1i = x0 + 1;

    const bool vy0 = (y0 >= 0 && y0 < Hp), vy1 = (y1 >= 0 && y1 < Hp);
    const bool vx0 = (x0 >= 0 && x0 < Wp), vx1 = (x1i >= 0 && x1i < Wp);

    const int yc0 = min(max(y0, 0), Hp - 1), yc1 = min(max(y1, 0), Hp - 1);
    const int xc0 = min(max(x0, 0), Wp - 1), xc1 = min(max(x1i, 0), Wp - 1);

    const float w00 = (vy0 && vx0) ? wy0 * wx0 : 0.f;
    const float w01 = (vy0 && vx1) ? wy0 * wx1 : 0.f;
    const float w10 = (vy1 && vx0) ? wy1 * wx0 : 0.f;
    const float w11 = (vy1 && vx1) ? wy1 * wx1 : 0.f;

    const int i00 = yc0 * Wp + xc0, i01 = yc0 * Wp + xc1;
    const int i10 = yc1 * Wp + xc0, i11 = yc1 * Wp + xc1;

    for (int c = 0; c < Cp; c++) {
        const float* xc = x1 + (size_t)(b * Cp + c) * HWp;
        const float v = w00 * xc[i00] + w01 * xc[i01] + w10 * xc[i10] + w11 * xc[i11];
        xb[(size_t)(b * CKp + c * 9 + k) * HWp + p] = v;
    }
}

// ============================================================================
// Grouped per-c 9x9 matmul (dct / inverse), optional elementwise mul fusion
// ============================================================================
template<bool MUL>
__global__ __launch_bounds__(256)
void grp9_kernel(const float* __restrict__ a, const float* __restrict__ bmul,
                 const float* __restrict__ w, float* __restrict__ out)
{
    const int p = blockIdx.x * 256 + threadIdx.x;
    const int c = blockIdx.y, b = blockIdx.z;
    __shared__ float ws[81];
    if (threadIdx.x < 81) ws[threadIdx.x] = w[c * 81 + threadIdx.x];
    __syncthreads();

    float v[9];
    #pragma unroll
    for (int k = 0; k < 9; k++) {
        const size_t idx = (size_t)(b * CKp + c * 9 + k) * HWp + p;
        v[k] = MUL ? (a[idx] * bmul[idx]) : a[idx];
    }
    #pragma unroll
    for (int j = 0; j < 9; j++) {
        float o = 0.f;
        #pragma unroll
        for (int k = 0; k < 9; k++) o += ws[j * 9 + k] * v[k];
        out[(size_t)(b * CKp + c * 9 + j) * HWp + p] = o;
    }
}

// ============================================================================
// Host side
// ============================================================================
static void launch_gemm(const float* in, const float* W, const float* bias,
                        const float* add, float* out,
                        int Cin, int Cout, int Ktot, int act, bool k3)
{
    dim3 grid(HWp / 64, (Cout + 63) / 64, Bp);
    if (!k3) {
        switch (act) {
        case 0: gemm_kernel<0, false><<<grid, 256>>>(in, W, bias, add, out, Cin, Cout, Ktot); break;
        case 1: gemm_kernel<1, false><<<grid, 256>>>(in, W, bias, add, out, Cin, Cout, Ktot); break;
        case 2: gemm_kernel<2, false><<<grid, 256>>>(in, W, bias, add, out, Cin, Cout, Ktot); break;
        case 3: gemm_kernel<3, false><<<grid, 256>>>(in, W, bias, add, out, Cin, Cout, Ktot); break;
        }
    } else {
        gemm_kernel<2, true><<<grid, 256>>>(in, W, bias, add, out, Cin, Cout, Ktot);
    }
}

static void launch_tgemm(const float* in, const float* W, const float* add,
                         float* out, int Cin, int Cout, int Ktot, int act)
{
    dim3 grid(HWp / 128, Cout / 64, Bp);
    if (act == 1) {
        tgemm_kernel<1, false><<<grid, 128>>>(in, W, nullptr, out, Cin, Cout, Ktot);
    } else if (add) {
        tgemm_kernel<0, true><<<grid, 128>>>(in, W, add, out, Cin, Cout, Ktot);
    } else {
        tgemm_kernel<0, false><<<grid, 128>>>(in, W, nullptr, out, Cin, Cout, Ktot);
    }
}

extern "C" void kernel_launch(void* const* d_in, const int* in_sizes, int n_in,
                              void* d_out, int out_size)
{
    (void)in_sizes; (void)n_in; (void)out_size;
    const float* x       = (const float*)d_in[0];
    const float* enc_dw  = (const float*)d_in[1];
    const float* enc_pw1 = (const float*)d_in[2];
    const float* enc_pw2 = (const float*)d_in[3];
    const float* dec_dw  = (const float*)d_in[4];
    const float* dec_pw1 = (const float*)d_in[5];
    const float* dec_pw2 = (const float*)d_in[6];
    const float* off_w1  = (const float*)d_in[7];
    const float* off_b1  = (const float*)d_in[8];
    const float* off_w2  = (const float*)d_in[9];
    const float* off_b2  = (const float*)d_in[10];
    const float* off_w3  = (const float*)d_in[11];
    const float* off_b3  = (const float*)d_in[12];
    const float* off_w4  = (const float*)d_in[13];
    const float* off_b4  = (const float*)d_in[14];
    const float* off_w5  = (const float*)d_in[15];
    const float* off_b5  = (const float*)d_in[16];
    const float* off_w6  = (const float*)d_in[17];
    const float* off_b6  = (const float*)d_in[18];
    const float* dct_w   = (const float*)d_in[19];
    const float* wie_w1  = (const float*)d_in[20];
    const float* wie_w2  = (const float*)d_in[21];
    const float* wie_w3  = (const float*)d_in[22];
    const float* wie_w4  = (const float*)d_in[23];
    const float* wie_w5  = (const float*)d_in[24];
    const float* wie_w6  = (const float*)d_in[25];
    const float* inv_w1  = (const float*)d_in[26];
    const float* inv_w2  = (const float*)d_in[27];

    float *x1, *t128, *e1, *e2, *off, *xb, *dct, *wa, *wb;
    cudaGetSymbolAddress((void**)&x1,   g_x1);
    cudaGetSymbolAddress((void**)&t128, g_t128);
    cudaGetSymbolAddress((void**)&e1,   g_e1);
    cudaGetSymbolAddress((void**)&e2,   g_e2);
    cudaGetSymbolAddress((void**)&off,  g_off);
    cudaGetSymbolAddress((void**)&xb,   g_xb);
    cudaGetSymbolAddress((void**)&dct,  g_dct);
    cudaGetSymbolAddress((void**)&wa,   g_wa);
    cudaGetSymbolAddress((void**)&wb,   g_wb);

    const dim3 gdw(HWp / 256, Cp, Bp);
    const dim3 gdw3(HWp / 256, CKp, Bp);
    const dim3 ggrp(HWp / 256, Cp, Bp);

    // ---- Encoder ConvNeXt (fp32: feeds the offset-sensitive path) ----
    dw7_kernel<<<gdw, 256>>>(x, enc_dw, e1);
    launch_gemm(e1, enc_pw1, nullptr, nullptr, t128, 64, 128, 64, 1, false);
    launch_gemm(t128, enc_pw2, nullptr, x, x1, 128, 64, 128, 0, false);

    // ---- Offset CNN (fp32: 8x tanh amplification makes this precision-critical) ----
    launch_gemm(x1, off_w1, off_b1, nullptr, e1, 64, 64, 64, 2, false);
    launch_gemm(e1, off_w2, off_b2, nullptr, e2, 64, 64, 576, 2, true);
    launch_gemm(e2, off_w3, off_b3, nullptr, e1, 64, 64, 576, 2, true);
    launch_gemm(e1, off_w4, off_b4, nullptr, e2, 64, 64, 576, 2, true);
    launch_gemm(e2, off_w5, off_b5, nullptr, e1, 64, 64, 576, 2, true);
    launch_gemm(e1, off_w6, off_b6, nullptr, off, 64, 18, 64, 3, false);

    // ---- Deformable gather ----
    deform_kernel<<<dim3(HWp / 128, 9, Bp), 128>>>(x1, off, xb);

    // ---- DCT (grouped per-c 9x9, fp32) ----
    grp9_kernel<false><<<ggrp, 256>>>(xb, nullptr, dct_w, dct);

    // ---- Wiener chain (tf32 tensor cores for the 576x576 GEMMs) ----
    launch_tgemm(xb, wie_w1, nullptr, wa, 576, 576, 576, 0);
    dw3_kernel<1><<<gdw3, 256>>>(wa, wie_w2, wb);
    launch_tgemm(wb, wie_w3, nullptr, wa, 576, 576, 576, 0);
    dw3_kernel<1><<<gdw3, 256>>>(wa, wie_w4, wb);
    launch_tgemm(wb, wie_w5, nullptr, wa, 576, 576, 576, 0);
    dw3_kernel<4><<<gdw3, 256>>>(wa, wie_w6, wb);   // sigmoid -> wiener in wb

    // ---- Inverse: (wiener*dct) -> grouped 9x9 (fp32) -> 1x1 (tf32) ----
    grp9_kernel<true><<<ggrp, 256>>>(wb, dct, inv_w1, wa);
    launch_tgemm(wa, inv_w2, nullptr, e1, 576, 64, 576, 0);

    // ---- Decoder ConvNeXt (tf32 pointwise; residual e1 stays exact) ----
    dw7_kernel<<<gdw, 256>>>(e1, dec_dw, e2);
    launch_tgemm(e2, dec_pw1, nullptr, t128, 64, 128, 64, 1);
    launch_tgemm(t128, dec_pw2, e1, (float*)d_out, 128, 64, 128, 0);
}